// round 1
// baseline (speedup 1.0000x reference)
#include <cuda_runtime.h>

// Problem constants
#define BI 4
#define SS 1024
#define DM 1024
#define NH 16
#define DH 64
#define MROWS (BI * SS)            // 4096
#define OUT_ELEMS (MROWS * DM)     // 4194304
#define ATTN_ELEMS ((size_t)BI * NH * SS * SS) // 67108864

// Scratch (device globals; allocation inside kernel_launch is forbidden)
__device__ float g_q[MROWS * DM];
__device__ float g_k[MROWS * DM];
__device__ float g_v[MROWS * DM];
__device__ float g_ctx[MROWS * DM];
__device__ float g_y[MROWS * DM];
__device__ float g_attn[ATTN_ELEMS];   // used only if attn is not part of d_out
__device__ int   g_mask_is_int32;

#define FMA16(av, bv, acc) do { \
  acc[0][0] += av.x * bv.x; acc[0][1] += av.x * bv.y; acc[0][2] += av.x * bv.z; acc[0][3] += av.x * bv.w; \
  acc[1][0] += av.y * bv.x; acc[1][1] += av.y * bv.y; acc[1][2] += av.y * bv.z; acc[1][3] += av.y * bv.w; \
  acc[2][0] += av.z * bv.x; acc[2][1] += av.z * bv.y; acc[2][2] += av.z * bv.z; acc[2][3] += av.z * bv.w; \
  acc[3][0] += av.w * bv.x; acc[3][1] += av.w * bv.y; acc[3][2] += av.w * bv.z; acc[3][3] += av.w * bv.w; \
} while (0)

// ---------------------------------------------------------------------------
// Mask dtype detection: int32 (values 0/1) vs uint8 bytes.
// If the buffer is really uint8, random packed bytes read as u32 are almost
// surely > 1 somewhere in the first 1024 words.
// ---------------------------------------------------------------------------
__global__ void detect_mask_kernel(const unsigned* m) {
    int ok = 1;
    for (int i = threadIdx.x; i < 1024; i += 32)
        if (m[i] > 1u) ok = 0;
    unsigned b = __ballot_sync(0xffffffffu, ok);
    if (threadIdx.x == 0) g_mask_is_int32 = (b == 0xffffffffu) ? 1 : 0;
}

// ---------------------------------------------------------------------------
// Shared GEMM tile bodies. 64x64 output tile, 256 threads, 4x4 per thread,
// K-chunks of 16. As/Bs stored transposed [k][m] so inner loop is 2x LDS.128.
// Padding 68: stride 272B = 17*16B keeps float4 alignment, reduces conflicts.
// ---------------------------------------------------------------------------
__device__ __forceinline__ void gemm_body_nn(
    const float* __restrict__ A, size_t lda,   // A pre-offset to (tile_row, 0)
    const float* __restrict__ B, size_t ldb,   // B pre-offset to (0, tile_col)
    int K,
    float (&As)[16][68], float (&Bs)[16][68], float (&acc)[4][4])
{
    const int tid = threadIdx.x;
    const int tx = tid & 15, ty = tid >> 4;
    const int am = tid >> 2, ak = (tid & 3) * 4;
    const int bk = tid >> 4, bn4 = (tid & 15) * 4;
    for (int k0 = 0; k0 < K; k0 += 16) {
        float4 a = *(const float4*)&A[(size_t)am * lda + k0 + ak];
        As[ak + 0][am] = a.x; As[ak + 1][am] = a.y;
        As[ak + 2][am] = a.z; As[ak + 3][am] = a.w;
        *(float4*)&Bs[bk][bn4] = *(const float4*)&B[(size_t)(k0 + bk) * ldb + bn4];
        __syncthreads();
        #pragma unroll
        for (int kk = 0; kk < 16; kk++) {
            float4 av = *(const float4*)&As[kk][ty * 4];
            float4 bv = *(const float4*)&Bs[kk][tx * 4];
            FMA16(av, bv, acc);
        }
        __syncthreads();
    }
}

__device__ __forceinline__ void gemm_body_nt(
    const float* __restrict__ A, size_t lda,   // A pre-offset to row tile
    const float* __restrict__ B, size_t ldb,   // B pre-offset to row tile (transposed op)
    int K,
    float (&As)[16][68], float (&Bs)[16][68], float (&acc)[4][4])
{
    const int tid = threadIdx.x;
    const int tx = tid & 15, ty = tid >> 4;
    const int am = tid >> 2, ak = (tid & 3) * 4;
    for (int k0 = 0; k0 < K; k0 += 16) {
        float4 a = *(const float4*)&A[(size_t)am * lda + k0 + ak];
        As[ak + 0][am] = a.x; As[ak + 1][am] = a.y;
        As[ak + 2][am] = a.z; As[ak + 3][am] = a.w;
        float4 b = *(const float4*)&B[(size_t)am * ldb + k0 + ak];
        Bs[ak + 0][am] = b.x; Bs[ak + 1][am] = b.y;
        Bs[ak + 2][am] = b.z; Bs[ak + 3][am] = b.w;
        __syncthreads();
        #pragma unroll
        for (int kk = 0; kk < 16; kk++) {
            float4 av = *(const float4*)&As[kk][ty * 4];
            float4 bv = *(const float4*)&Bs[kk][tx * 4];
            FMA16(av, bv, acc);
        }
        __syncthreads();
    }
}

// ---------------------------------------------------------------------------
// 1) Fused QKV projections: z selects (Q@Wq+bq) / (K@Wk+bk) / (V@Wv+bv)
//    M=4096, N=1024, K=1024. Grid (16, 64, 3).
// ---------------------------------------------------------------------------
__global__ void qkv_gemm_kernel(
    const float* __restrict__ Qin, const float* __restrict__ Kin, const float* __restrict__ Vin,
    const float* __restrict__ Wq, const float* __restrict__ Wk, const float* __restrict__ Wv,
    const float* __restrict__ bq, const float* __restrict__ bk, const float* __restrict__ bv)
{
    __shared__ float As[16][68];
    __shared__ float Bs[16][68];
    const float* A; const float* W; const float* bias; float* C;
    if (blockIdx.z == 0)      { A = Qin; W = Wq; bias = bq; C = g_q; }
    else if (blockIdx.z == 1) { A = Kin; W = Wk; bias = bk; C = g_k; }
    else                      { A = Vin; W = Wv; bias = bv; C = g_v; }
    const int bm = blockIdx.y * 64, bn = blockIdx.x * 64;
    float acc[4][4] = {};
    gemm_body_nn(A + (size_t)bm * DM, DM, W + bn, DM, DM, As, Bs, acc);
    const int tx = threadIdx.x & 15, ty = threadIdx.x >> 4;
    #pragma unroll
    for (int i = 0; i < 4; i++) {
        #pragma unroll
        for (int j = 0; j < 4; j++) {
            int r = bm + ty * 4 + i, c = bn + tx * 4 + j;
            C[(size_t)r * DM + c] = acc[i][j] + bias[c];
        }
    }
}

// ---------------------------------------------------------------------------
// 2) Scores: attn[b,h,i,j] = mask ? -1e9 : dot(q_i, k_j) / 8.  Grid (16,16,64).
// ---------------------------------------------------------------------------
__global__ void scores_kernel(const void* __restrict__ mask, float* __restrict__ attn_ext, int use_ext) {
    __shared__ float As[16][68];
    __shared__ float Bs[16][68];
    const int bh = blockIdx.z, b = bh >> 4, h = bh & 15;
    const int bi = blockIdx.y * 64, bj = blockIdx.x * 64;
    const float* qb = g_q + (size_t)b * SS * DM + h * DH;
    const float* kb = g_k + (size_t)b * SS * DM + h * DH;
    float acc[4][4] = {};
    gemm_body_nt(qb + (size_t)bi * DM, DM, kb + (size_t)bj * DM, DM, DH, As, Bs, acc);

    float* attn = use_ext ? attn_ext : g_attn;
    float* outb = attn + (size_t)bh * SS * SS;
    const size_t mbase = (size_t)b * SS * SS;
    const int mi32 = g_mask_is_int32;
    const int* m32 = (const int*)mask;
    const unsigned char* m8 = (const unsigned char*)mask;
    const int tx = threadIdx.x & 15, ty = threadIdx.x >> 4;
    #pragma unroll
    for (int i = 0; i < 4; i++) {
        #pragma unroll
        for (int j = 0; j < 4; j++) {
            int r = bi + ty * 4 + i, c = bj + tx * 4 + j;
            size_t midx = mbase + (size_t)r * SS + c;
            bool m = mi32 ? (m32[midx] != 0) : (m8[midx] != 0);
            outb[(size_t)r * SS + c] = m ? -1e9f : acc[i][j] * 0.125f;
        }
    }
}

// ---------------------------------------------------------------------------
// 3) Row softmax over S=1024, in place. Grid 65536 x 256.
// ---------------------------------------------------------------------------
__global__ void softmax_kernel(float* __restrict__ attn_ext, int use_ext) {
    float* attn = use_ext ? attn_ext : g_attn;
    float* row = attn + (size_t)blockIdx.x * SS;
    __shared__ float sh[256];
    const int t = threadIdx.x;
    float x0 = row[t], x1 = row[t + 256], x2 = row[t + 512], x3 = row[t + 768];
    float m = fmaxf(fmaxf(x0, x1), fmaxf(x2, x3));
    sh[t] = m; __syncthreads();
    for (int s = 128; s > 0; s >>= 1) { if (t < s) sh[t] = fmaxf(sh[t], sh[t + s]); __syncthreads(); }
    m = sh[0]; __syncthreads();
    float e0 = __expf(x0 - m), e1 = __expf(x1 - m), e2 = __expf(x2 - m), e3 = __expf(x3 - m);
    sh[t] = e0 + e1 + e2 + e3; __syncthreads();
    for (int s = 128; s > 0; s >>= 1) { if (t < s) sh[t] += sh[t + s]; __syncthreads(); }
    float inv = 1.0f / sh[0];
    row[t] = e0 * inv; row[t + 256] = e1 * inv; row[t + 512] = e2 * inv; row[t + 768] = e3 * inv;
}

// ---------------------------------------------------------------------------
// 4) Context: ctx[b,i,h*64+d] = sum_j attn[b,h,i,j] * v[b,j,h*64+d].
//    Per bh: M=1024, N=64, K=1024. Grid (1,16,64).
// ---------------------------------------------------------------------------
__global__ void context_kernel(const float* __restrict__ attn_ext, int use_ext) {
    __shared__ float As[16][68];
    __shared__ float Bs[16][68];
    const int bh = blockIdx.z, b = bh >> 4, h = bh & 15;
    const int bi = blockIdx.y * 64;
    const float* attn = use_ext ? attn_ext : g_attn;
    const float* ab = attn + (size_t)bh * SS * SS;
    const float* vb = g_v + (size_t)b * SS * DM + h * DH;
    float acc[4][4] = {};
    gemm_body_nn(ab + (size_t)bi * SS, SS, vb, DM, SS, As, Bs, acc);
    const int tx = threadIdx.x & 15, ty = threadIdx.x >> 4;
    #pragma unroll
    for (int i = 0; i < 4; i++) {
        #pragma unroll
        for (int j = 0; j < 4; j++) {
            int r = bi + ty * 4 + i, c = tx * 4 + j;
            g_ctx[(size_t)(b * SS + r) * DM + h * DH + c] = acc[i][j];
        }
    }
}

// ---------------------------------------------------------------------------
// 5) Output projection + residual: y = ctx @ Wo + bo + Qin. Grid (16,64).
// ---------------------------------------------------------------------------
__global__ void outproj_kernel(const float* __restrict__ Wo, const float* __restrict__ bo,
                               const float* __restrict__ Qres) {
    __shared__ float As[16][68];
    __shared__ float Bs[16][68];
    const int bm = blockIdx.y * 64, bn = blockIdx.x * 64;
    float acc[4][4] = {};
    gemm_body_nn(g_ctx + (size_t)bm * DM, DM, Wo + bn, DM, DM, As, Bs, acc);
    const int tx = threadIdx.x & 15, ty = threadIdx.x >> 4;
    #pragma unroll
    for (int i = 0; i < 4; i++) {
        #pragma unroll
        for (int j = 0; j < 4; j++) {
            int r = bm + ty * 4 + i, c = bn + tx * 4 + j;
            g_y[(size_t)r * DM + c] = acc[i][j] + bo[c] + Qres[(size_t)r * DM + c];
        }
    }
}

// ---------------------------------------------------------------------------
// 6) LayerNorm over last dim (1024), biased variance, eps 1e-5. Grid 4096x256.
// ---------------------------------------------------------------------------
__global__ void ln_kernel(const float* __restrict__ gamma, const float* __restrict__ beta,
                          float* __restrict__ out) {
    const float* row = g_y + (size_t)blockIdx.x * DM;
    __shared__ float s1[256];
    __shared__ float s2[256];
    const int t = threadIdx.x;
    float x0 = row[t], x1 = row[t + 256], x2 = row[t + 512], x3 = row[t + 768];
    s1[t] = x0 + x1 + x2 + x3;
    s2[t] = x0 * x0 + x1 * x1 + x2 * x2 + x3 * x3;
    __syncthreads();
    for (int s = 128; s > 0; s >>= 1) {
        if (t < s) { s1[t] += s1[t + s]; s2[t] += s2[t + s]; }
        __syncthreads();
    }
    float mean = s1[0] * (1.0f / 1024.0f);
    float var = s2[0] * (1.0f / 1024.0f) - mean * mean;
    float rstd = rsqrtf(var + 1e-5f);
    float* o = out + (size_t)blockIdx.x * DM;
    o[t]       = (x0 - mean) * rstd * gamma[t]       + beta[t];
    o[t + 256] = (x1 - mean) * rstd * gamma[t + 256] + beta[t + 256];
    o[t + 512] = (x2 - mean) * rstd * gamma[t + 512] + beta[t + 512];
    o[t + 768] = (x3 - mean) * rstd * gamma[t + 768] + beta[t + 768];
}

// ---------------------------------------------------------------------------
extern "C" void kernel_launch(void* const* d_in, const int* in_sizes, int n_in,
                              void* d_out, int out_size) {
    const float* Qin   = (const float*)d_in[0];
    const float* Kin   = (const float*)d_in[1];
    const float* Vin   = (const float*)d_in[2];
    const void*  mask  = d_in[3];
    const float* Wq    = (const float*)d_in[4];
    const float* bq    = (const float*)d_in[5];
    const float* Wk    = (const float*)d_in[6];
    const float* bk    = (const float*)d_in[7];
    const float* Wv    = (const float*)d_in[8];
    const float* bv    = (const float*)d_in[9];
    const float* Wo    = (const float*)d_in[10];
    const float* bo    = (const float*)d_in[11];
    const float* gamma = (const float*)d_in[12];
    const float* beta  = (const float*)d_in[13];
    float* out = (float*)d_out;

    // If d_out holds the flattened tuple (out, attn), attn lives right after out.
    const int use_ext = (out_size > OUT_ELEMS) ? 1 : 0;
    float* attn_ext = out + OUT_ELEMS;

    detect_mask_kernel<<<1, 32>>>((const unsigned*)mask);
    qkv_gemm_kernel<<<dim3(16, 64, 3), 256>>>(Qin, Kin, Vin, Wq, Wk, Wv, bq, bk, bv);
    scores_kernel<<<dim3(16, 16, 64), 256>>>(mask, attn_ext, use_ext);
    softmax_kernel<<<dim3(BI * NH * SS), 256>>>(attn_ext, use_ext);
    context_kernel<<<dim3(1, 16, 64), 256>>>(attn_ext, use_ext);
    outproj_kernel<<<dim3(16, 64), 256>>>(Wo, bo, Qin);
    ln_kernel<<<dim3(MROWS), 256>>>(gamma, beta, out);
    (void)in_sizes; (void)n_in;
}

// round 2
// speedup vs baseline: 1.5695x; 1.5695x over previous
#include <cuda_runtime.h>

// Problem constants
#define BI 4
#define SS 1024
#define DM 1024
#define NH 16
#define DH 64
#define MROWS (BI * SS)            // 4096
#define OUT_ELEMS (MROWS * DM)     // 4194304
#define ATTN_ELEMS ((size_t)BI * NH * SS * SS) // 67108864

// Scratch (device globals; allocation inside kernel_launch is forbidden)
__device__ float g_q[MROWS * DM];
__device__ float g_k[MROWS * DM];
__device__ float g_v[MROWS * DM];
__device__ float g_ctx[MROWS * DM];
__device__ float g_y[MROWS * DM];
__device__ float g_attn[ATTN_ELEMS];   // used only if attn is not part of d_out
__device__ int   g_mask_is_int32;

// ---------------------------------------------------------------------------
// tf32 helpers
// ---------------------------------------------------------------------------
__device__ __forceinline__ unsigned f2tf(float x) {
    unsigned u;
    asm("cvt.rna.tf32.f32 %0, %1;" : "=r"(u) : "f"(x));
    return u;
}
__device__ __forceinline__ uint4 tf32x4(float4 v) {
    uint4 t;
    t.x = f2tf(v.x); t.y = f2tf(v.y); t.z = f2tf(v.z); t.w = f2tf(v.w);
    return t;
}

#define MMA_TF32(d, a, b0, b1) \
    asm volatile("mma.sync.aligned.m16n8k8.row.col.f32.tf32.tf32.f32 " \
                 "{%0,%1,%2,%3}, {%4,%5,%6,%7}, {%8,%9}, {%0,%1,%2,%3};" \
                 : "+f"(d[0]), "+f"(d[1]), "+f"(d[2]), "+f"(d[3]) \
                 : "r"(a[0]), "r"(a[1]), "r"(a[2]), "r"(a[3]), "r"(b0), "r"(b1))

// ---------------------------------------------------------------------------
// Mask dtype detection: int32 (values 0/1) vs uint8 bytes.
// ---------------------------------------------------------------------------
__global__ void detect_mask_kernel(const unsigned* m) {
    int ok = 1;
    for (int i = threadIdx.x; i < 1024; i += 32)
        if (m[i] > 1u) ok = 0;
    unsigned b = __ballot_sync(0xffffffffu, ok);
    if (threadIdx.x == 0) g_mask_is_int32 = (b == 0xffffffffu) ? 1 : 0;
}

// ---------------------------------------------------------------------------
// tf32 MMA tile body. Block = BM x BN (BM=128), 256 threads = 8 warps (4m x 2n).
// Warp tile = 32 x (BN/2). mma.m16n8k8: MF=2 m-frags, NF=BN/16 n-frags.
// Smem stride 20 floats: fragment loads provably conflict-free
// (banks (20*r + c) % 32 cover all 32 for r in 0..7, c in 0..3).
// BNT=true: B source is [n][k] (k contiguous) -> direct copy.
// BNT=false: B source is [k][n]  -> transpose on store (conflict-free mapping).
// ---------------------------------------------------------------------------
template<int BM, int BN, bool BNT>
__device__ __forceinline__ void mma_tile(
    const float* __restrict__ A, int lda,   // pre-offset to block row, col 0
    const float* __restrict__ B, int ldb,   // NT: pre-offset to block rows; NN: to block col
    int K,
    float* __restrict__ As, float* __restrict__ Bs,   // As[BM*20], Bs[BN*20]
    float (&acc)[2][BN / 16][4])
{
    constexpr int NF = BN / 16;
    const int tid  = threadIdx.x;
    const int lane = tid & 31;
    const int wid  = tid >> 5;
    const int wm   = (wid & 3) * 32;
    const int wn   = (wid >> 2) * (BN / 2);
    const int r    = lane >> 2;
    const int cq   = lane & 3;

    unsigned* Asu = (unsigned*)As;
    unsigned* Bsu = (unsigned*)Bs;

    for (int k0 = 0; k0 < K; k0 += 16) {
        // Load A chunk [BM][16]
        #pragma unroll
        for (int f = tid; f < BM * 4; f += 256) {
            int m = f >> 2, k4 = (f & 3) << 2;
            float4 v = *(const float4*)(A + (size_t)m * lda + k0 + k4);
            *(uint4*)(Asu + m * 20 + k4) = tf32x4(v);
        }
        // Load B chunk
        if (BNT) {
            #pragma unroll
            for (int f = tid; f < BN * 4; f += 256) {
                int n = f >> 2, k4 = (f & 3) << 2;
                float4 v = *(const float4*)(B + (size_t)n * ldb + k0 + k4);
                *(uint4*)(Bsu + n * 20 + k4) = tf32x4(v);
            }
        } else {
            #pragma unroll
            for (int f = tid; f < BN * 4; f += 256) {
                int k = f & 15, n4 = f >> 4;
                float4 v = *(const float4*)(B + (size_t)(k0 + k) * ldb + 4 * n4);
                uint4 t = tf32x4(v);
                Bsu[(4 * n4 + 0) * 20 + k] = t.x;
                Bsu[(4 * n4 + 1) * 20 + k] = t.y;
                Bsu[(4 * n4 + 2) * 20 + k] = t.z;
                Bsu[(4 * n4 + 3) * 20 + k] = t.w;
            }
        }
        __syncthreads();

        #pragma unroll
        for (int ks = 0; ks < 2; ks++) {
            const int c = ks * 8 + cq;
            unsigned a[2][4];
            #pragma unroll
            for (int mf = 0; mf < 2; mf++) {
                const unsigned* p = Asu + (wm + mf * 16 + r) * 20 + c;
                a[mf][0] = p[0];
                a[mf][1] = p[8 * 20];
                a[mf][2] = p[4];
                a[mf][3] = p[8 * 20 + 4];
            }
            #pragma unroll
            for (int nf = 0; nf < NF; nf++) {
                const unsigned* p = Bsu + (wn + nf * 8 + r) * 20 + c;
                unsigned b0 = p[0], b1 = p[4];
                #pragma unroll
                for (int mf = 0; mf < 2; mf++) {
                    MMA_TF32(acc[mf][nf], a[mf], b0, b1);
                }
            }
        }
        __syncthreads();
    }
}

// Epilogue coordinate helpers: for (mf, nf), values c0,c1 at (row, col),(row,col+1);
// c2,c3 at (row+8, col),(row+8, col+1) with
// row = wm + mf*16 + lane/4, col = wn + nf*8 + 2*(lane%4).

// ---------------------------------------------------------------------------
// 1) Fused QKV projections (NN): M=4096, N=1024, K=1024. Grid (8, 32, 3).
// ---------------------------------------------------------------------------
__global__ __launch_bounds__(256) void qkv_gemm_kernel(
    const float* __restrict__ Qin, const float* __restrict__ Kin, const float* __restrict__ Vin,
    const float* __restrict__ Wq, const float* __restrict__ Wk, const float* __restrict__ Wv,
    const float* __restrict__ bq, const float* __restrict__ bk, const float* __restrict__ bv)
{
    __shared__ float As[128 * 20];
    __shared__ float Bs[128 * 20];
    const float* A; const float* W; const float* bias; float* C;
    if (blockIdx.z == 0)      { A = Qin; W = Wq; bias = bq; C = g_q; }
    else if (blockIdx.z == 1) { A = Kin; W = Wk; bias = bk; C = g_k; }
    else                      { A = Vin; W = Wv; bias = bv; C = g_v; }
    const int bm = blockIdx.y * 128, bn = blockIdx.x * 128;
    float acc[2][8][4] = {};
    mma_tile<128, 128, false>(A + (size_t)bm * DM, DM, W + bn, DM, DM, As, Bs, acc);

    const int lane = threadIdx.x & 31, wid = threadIdx.x >> 5;
    const int wm = (wid & 3) * 32, wn = (wid >> 2) * 64;
    const int r = lane >> 2, cq = lane & 3;
    #pragma unroll
    for (int mf = 0; mf < 2; mf++) {
        #pragma unroll
        for (int nf = 0; nf < 8; nf++) {
            int row = bm + wm + mf * 16 + r;
            int col = bn + wn + nf * 8 + 2 * cq;
            float2 bia = *(const float2*)&bias[col];
            *(float2*)&C[(size_t)row * DM + col] =
                make_float2(acc[mf][nf][0] + bia.x, acc[mf][nf][1] + bia.y);
            *(float2*)&C[(size_t)(row + 8) * DM + col] =
                make_float2(acc[mf][nf][2] + bia.x, acc[mf][nf][3] + bia.y);
        }
    }
}

// ---------------------------------------------------------------------------
// 2) Scores (NT): per bh M=1024, N=1024, K=64. Grid (8, 8, 64).
// ---------------------------------------------------------------------------
__global__ __launch_bounds__(256) void scores_kernel(
    const void* __restrict__ mask, float* __restrict__ attn_ext, int use_ext)
{
    __shared__ float As[128 * 20];
    __shared__ float Bs[128 * 20];
    const int bh = blockIdx.z, b = bh >> 4, h = bh & 15;
    const int bi = blockIdx.y * 128, bj = blockIdx.x * 128;
    const float* qb = g_q + (size_t)b * SS * DM + h * DH;
    const float* kb = g_k + (size_t)b * SS * DM + h * DH;
    float acc[2][8][4] = {};
    mma_tile<128, 128, true>(qb + (size_t)bi * DM, DM, kb + (size_t)bj * DM, DM, DH, As, Bs, acc);

    float* attn = use_ext ? attn_ext : g_attn;
    float* outb = attn + (size_t)bh * SS * SS;
    const size_t mbase = (size_t)b * SS * SS;
    const int mi32 = g_mask_is_int32;
    const int* m32 = (const int*)mask;
    const unsigned char* m8 = (const unsigned char*)mask;

    const int lane = threadIdx.x & 31, wid = threadIdx.x >> 5;
    const int wm = (wid & 3) * 32, wn = (wid >> 2) * 64;
    const int r = lane >> 2, cq = lane & 3;
    #pragma unroll
    for (int mf = 0; mf < 2; mf++) {
        #pragma unroll
        for (int nf = 0; nf < 8; nf++) {
            int row = bi + wm + mf * 16 + r;
            int col = bj + wn + nf * 8 + 2 * cq;
            #pragma unroll
            for (int half = 0; half < 2; half++) {
                int rr = row + half * 8;
                size_t mi = mbase + (size_t)rr * SS + col;
                bool ma, mb;
                if (mi32) { ma = m32[mi] != 0; mb = m32[mi + 1] != 0; }
                else      { ma = m8[mi]  != 0; mb = m8[mi + 1]  != 0; }
                float v0 = ma ? -1e9f : acc[mf][nf][2 * half + 0] * 0.125f;
                float v1 = mb ? -1e9f : acc[mf][nf][2 * half + 1] * 0.125f;
                *(float2*)&outb[(size_t)rr * SS + col] = make_float2(v0, v1);
            }
        }
    }
}

// ---------------------------------------------------------------------------
// 3) Row softmax over S=1024, in place. Grid 65536 x 256, float4 + shfl.
// ---------------------------------------------------------------------------
__global__ __launch_bounds__(256) void softmax_kernel(float* __restrict__ attn_ext, int use_ext) {
    float* attn = use_ext ? attn_ext : g_attn;
    float4* row = (float4*)(attn + (size_t)blockIdx.x * SS);
    const int t = threadIdx.x, lane = t & 31, w = t >> 5;
    __shared__ float sm[8], ss[8];

    float4 x = row[t];
    float m = fmaxf(fmaxf(x.x, x.y), fmaxf(x.z, x.w));
    #pragma unroll
    for (int o = 16; o > 0; o >>= 1) m = fmaxf(m, __shfl_xor_sync(0xffffffffu, m, o));
    if (lane == 0) sm[w] = m;
    __syncthreads();
    float M = sm[0];
    #pragma unroll
    for (int i = 1; i < 8; i++) M = fmaxf(M, sm[i]);

    float e0 = __expf(x.x - M), e1 = __expf(x.y - M);
    float e2 = __expf(x.z - M), e3 = __expf(x.w - M);
    float s = e0 + e1 + e2 + e3;
    #pragma unroll
    for (int o = 16; o > 0; o >>= 1) s += __shfl_xor_sync(0xffffffffu, s, o);
    if (lane == 0) ss[w] = s;
    __syncthreads();
    float S = ss[0];
    #pragma unroll
    for (int i = 1; i < 8; i++) S += ss[i];
    float inv = 1.0f / S;
    row[t] = make_float4(e0 * inv, e1 * inv, e2 * inv, e3 * inv);
}

// ---------------------------------------------------------------------------
// 4) Context (NN): per bh M=1024, N=64, K=1024. Grid (1, 8, 64). BN=64.
// ---------------------------------------------------------------------------
__global__ __launch_bounds__(256) void context_kernel(const float* __restrict__ attn_ext, int use_ext) {
    __shared__ float As[128 * 20];
    __shared__ float Bs[64 * 20];
    const int bh = blockIdx.z, b = bh >> 4, h = bh & 15;
    const int bi = blockIdx.y * 128;
    const float* attn = use_ext ? attn_ext : g_attn;
    const float* ab = attn + (size_t)bh * SS * SS;
    const float* vb = g_v + (size_t)b * SS * DM + h * DH;
    float acc[2][4][4] = {};
    mma_tile<128, 64, false>(ab + (size_t)bi * SS, SS, vb, DM, SS, As, Bs, acc);

    const int lane = threadIdx.x & 31, wid = threadIdx.x >> 5;
    const int wm = (wid & 3) * 32, wn = (wid >> 2) * 32;
    const int r = lane >> 2, cq = lane & 3;
    float* cb = g_ctx + (size_t)b * SS * DM + h * DH;
    #pragma unroll
    for (int mf = 0; mf < 2; mf++) {
        #pragma unroll
        for (int nf = 0; nf < 4; nf++) {
            int row = bi + wm + mf * 16 + r;
            int col = wn + nf * 8 + 2 * cq;
            *(float2*)&cb[(size_t)row * DM + col] =
                make_float2(acc[mf][nf][0], acc[mf][nf][1]);
            *(float2*)&cb[(size_t)(row + 8) * DM + col] =
                make_float2(acc[mf][nf][2], acc[mf][nf][3]);
        }
    }
}

// ---------------------------------------------------------------------------
// 5) Output projection + residual (NN): y = ctx @ Wo + bo + Qin. Grid (8, 32).
// ---------------------------------------------------------------------------
__global__ __launch_bounds__(256) void outproj_kernel(
    const float* __restrict__ Wo, const float* __restrict__ bo,
    const float* __restrict__ Qres)
{
    __shared__ float As[128 * 20];
    __shared__ float Bs[128 * 20];
    const int bm = blockIdx.y * 128, bn = blockIdx.x * 128;
    float acc[2][8][4] = {};
    mma_tile<128, 128, false>(g_ctx + (size_t)bm * DM, DM, Wo + bn, DM, DM, As, Bs, acc);

    const int lane = threadIdx.x & 31, wid = threadIdx.x >> 5;
    const int wm = (wid & 3) * 32, wn = (wid >> 2) * 64;
    const int r = lane >> 2, cq = lane & 3;
    #pragma unroll
    for (int mf = 0; mf < 2; mf++) {
        #pragma unroll
        for (int nf = 0; nf < 8; nf++) {
            int row = bm + wm + mf * 16 + r;
            int col = bn + wn + nf * 8 + 2 * cq;
            float2 bia = *(const float2*)&bo[col];
            float2 q0 = *(const float2*)&Qres[(size_t)row * DM + col];
            float2 q1 = *(const float2*)&Qres[(size_t)(row + 8) * DM + col];
            *(float2*)&g_y[(size_t)row * DM + col] =
                make_float2(acc[mf][nf][0] + bia.x + q0.x, acc[mf][nf][1] + bia.y + q0.y);
            *(float2*)&g_y[(size_t)(row + 8) * DM + col] =
                make_float2(acc[mf][nf][2] + bia.x + q1.x, acc[mf][nf][3] + bia.y + q1.y);
        }
    }
}

// ---------------------------------------------------------------------------
// 6) LayerNorm over last dim (1024), biased variance, eps 1e-5. Grid 4096x256.
// ---------------------------------------------------------------------------
__global__ __launch_bounds__(256) void ln_kernel(
    const float* __restrict__ gamma, const float* __restrict__ beta,
    float* __restrict__ out)
{
    const float4* row = (const float4*)(g_y + (size_t)blockIdx.x * DM);
    const int t = threadIdx.x, lane = t & 31, w = t >> 5;
    __shared__ float s1[8], s2[8];
    float4 x = row[t];
    float a = x.x + x.y + x.z + x.w;
    float b = x.x * x.x + x.y * x.y + x.z * x.z + x.w * x.w;
    #pragma unroll
    for (int o = 16; o > 0; o >>= 1) {
        a += __shfl_xor_sync(0xffffffffu, a, o);
        b += __shfl_xor_sync(0xffffffffu, b, o);
    }
    if (lane == 0) { s1[w] = a; s2[w] = b; }
    __syncthreads();
    float A = 0.f, B2 = 0.f;
    #pragma unroll
    for (int i = 0; i < 8; i++) { A += s1[i]; B2 += s2[i]; }
    float mean = A * (1.0f / 1024.0f);
    float var = B2 * (1.0f / 1024.0f) - mean * mean;
    float rstd = rsqrtf(var + 1e-5f);
    float4 g = ((const float4*)gamma)[t];
    float4 be = ((const float4*)beta)[t];
    float4 o4;
    o4.x = (x.x - mean) * rstd * g.x + be.x;
    o4.y = (x.y - mean) * rstd * g.y + be.y;
    o4.z = (x.z - mean) * rstd * g.z + be.z;
    o4.w = (x.w - mean) * rstd * g.w + be.w;
    ((float4*)(out + (size_t)blockIdx.x * DM))[t] = o4;
}

// ---------------------------------------------------------------------------
extern "C" void kernel_launch(void* const* d_in, const int* in_sizes, int n_in,
                              void* d_out, int out_size) {
    const float* Qin   = (const float*)d_in[0];
    const float* Kin   = (const float*)d_in[1];
    const float* Vin   = (const float*)d_in[2];
    const void*  mask  = d_in[3];
    const float* Wq    = (const float*)d_in[4];
    const float* bq    = (const float*)d_in[5];
    const float* Wk    = (const float*)d_in[6];
    const float* bk    = (const float*)d_in[7];
    const float* Wv    = (const float*)d_in[8];
    const float* bv    = (const float*)d_in[9];
    const float* Wo    = (const float*)d_in[10];
    const float* bo    = (const float*)d_in[11];
    const float* gamma = (const float*)d_in[12];
    const float* beta  = (const float*)d_in[13];
    float* out = (float*)d_out;

    const int use_ext = (out_size > OUT_ELEMS) ? 1 : 0;
    float* attn_ext = out + OUT_ELEMS;

    detect_mask_kernel<<<1, 32>>>((const unsigned*)mask);
    qkv_gemm_kernel<<<dim3(8, 32, 3), 256>>>(Qin, Kin, Vin, Wq, Wk, Wv, bq, bk, bv);
    scores_kernel<<<dim3(8, 8, 64), 256>>>(mask, attn_ext, use_ext);
    softmax_kernel<<<dim3(BI * NH * SS), 256>>>(attn_ext, use_ext);
    context_kernel<<<dim3(1, 8, 64), 256>>>(attn_ext, use_ext);
    outproj_kernel<<<dim3(8, 32), 256>>>(Wo, bo, Qin);
    ln_kernel<<<dim3(MROWS), 256>>>(gamma, beta, out);
    (void)in_sizes; (void)n_in;
}